// round 1
// baseline (speedup 1.0000x reference)
#include <cuda_runtime.h>
#include <math.h>

// ---------------------------------------------------------------------------
// NeuralODE: B=1024 rows, T=128 saves, 2 RK4 substeps/save, MLP 43->128->128->41
// Only 9 state dims evolve (latent frozen) -> fold latent@W1 into per-row bias.
// Persistent CTA design: 147 CTAs x 256 threads, 7 rows/CTA, single wave.
// ---------------------------------------------------------------------------

#define Bsz    1024
#define Tn     128
#define Dn     256
#define WIDTH  128
#define NACT   9      // 1 data + 8 aug dims evolve
#define LATD   32
#define INW    43     // W1 row length
#define RROWS  7
#define NCTA   147    // ceil(1024/7)
#define NTH    256
#define W2S    132    // padded row stride (floats): conflict-free float4 reads
#define HS     132
#define W3S    132

struct Smem {
    float W2p[WIDTH * W2S];     // 67584 B, W2 row-major padded
    float h1s[8 * HS];          // hidden 1 per row
    float h2s[8 * HS];          // hidden 2 per row
    float base1[8 * WIDTH];     // b1 + W1[:,9:41]@latent  per row
    float cs[8 * Dn];           // dense_cs rows for this CTA
    float W3s[NACT * W3S];      // first 9 rows of W3, padded
    float b3s[16];
    float Ycur[8][16];
    float Yts[8][16];           // RK stage input state
    float ksum[8][16];          // RK accumulator
    float tend[8];
    float tsm[Tn];
};

__global__ __launch_bounds__(NTH, 1)
void node_kernel(const float* __restrict__ ts, const float* __restrict__ y0,
                 const float* __restrict__ latent, const int* __restrict__ length,
                 const float* __restrict__ dense_ts, const float* __restrict__ dense_cs,
                 const float* __restrict__ W1, const float* __restrict__ b1,
                 const float* __restrict__ W2, const float* __restrict__ b2,
                 const float* __restrict__ W3, const float* __restrict__ b3,
                 float* __restrict__ out)
{
    extern __shared__ char smraw[];
    Smem& s = *reinterpret_cast<Smem*>(smraw);
    const int tid = threadIdx.x;
    const int j   = tid & 127;     // hidden unit index
    const int rg  = tid >> 7;      // row-group: 0 -> rows 0..3, 1 -> rows 4..6
    const int row0  = blockIdx.x * RROWS;
    const int nrows = min(RROWS, Bsz - row0);

    // ---- one-time setup ---------------------------------------------------
    for (int idx = tid; idx < WIDTH * WIDTH; idx += NTH)
        s.W2p[(idx >> 7) * W2S + (idx & 127)] = W2[idx];
    for (int idx = tid; idx < NACT * WIDTH; idx += NTH)
        s.W3s[(idx >> 7) * W3S + (idx & 127)] = W3[idx];
    if (tid < NACT) s.b3s[tid] = b3[tid];
    if (tid < Tn)   s.tsm[tid] = ts[tid];
    if (tid < nrows) {
        int b  = row0 + tid;
        int li = max(length[b] - 1, 0);
        s.tend[tid] = ts[li];
        float y = y0[b];
        s.Ycur[tid][0] = y; s.Yts[tid][0] = y;
        #pragma unroll
        for (int d = 1; d < NACT; d++) { s.Ycur[tid][d] = 0.f; s.Yts[tid][d] = 0.f; }
        out[b * Tn] = y;                      // t = 0 sample
    }
    for (int idx = tid; idx < nrows * Dn; idx += NTH)
        s.cs[idx] = dense_cs[row0 * Dn + idx];

    // per-thread W1 coefficients + per-row folded bias
    float w1a[NACT], w1t, w1c, b2j;
    {
        const float* W1r = W1 + j * INW;
        #pragma unroll
        for (int d = 0; d < NACT; d++) w1a[d] = W1r[d];
        w1t = W1r[41];
        w1c = W1r[42];
        b2j = b2[j];
        #pragma unroll
        for (int q = 0; q < 4; q++) {
            int rr = rg * 4 + q;
            if (rr < nrows) {
                const float* lv = latent + (row0 + rr) * LATD;
                float acc = b1[j];
                #pragma unroll
                for (int l = 0; l < LATD; l++) acc = fmaf(W1r[9 + l], lv[l], acc);
                s.base1[rr * WIDTH + j] = acc;
            }
        }
    }
    __syncthreads();

    // ---- time integration -------------------------------------------------
    for (int step = 0; step < Tn - 1; step++) {
        float ta  = s.tsm[step];
        float dtf = (s.tsm[step + 1] - ta) * 0.5f;     // RK4 substep dt
        for (int sub = 0; sub < 2; sub++) {
            float t0 = ta + sub * dtf;
            for (int st = 0; st < 4; st++) {
                float t = t0 + ((st == 0) ? 0.f : (st == 3) ? dtf : 0.5f * dtf);

                // concentration interp index (dense_ts == arange(D))
                int ii = (int)ceilf(t);
                ii = max(1, min(Dn - 1, ii));
                float w = t - (float)(ii - 1);
                w = fminf(fmaxf(w, 0.f), 1.f);

                // ---- layer 1: h1 = tanh(base1 + W1a@Yact + w1t*t + w1c*c)
                #pragma unroll
                for (int q = 0; q < 4; q++) {
                    int rr = rg * 4 + q;
                    if (rr < nrows) {
                        float cl = s.cs[rr * Dn + ii - 1];
                        float c  = fmaf(w, s.cs[rr * Dn + ii] - cl, cl);
                        float acc = s.base1[rr * WIDTH + j];
                        acc = fmaf(w1t, t, acc);
                        acc = fmaf(w1c, c, acc);
                        #pragma unroll
                        for (int d = 0; d < NACT; d++)
                            acc = fmaf(w1a[d], s.Yts[rr][d], acc);
                        s.h1s[rr * HS + j] = tanhf(acc);
                    }
                }
                __syncthreads();

                // ---- layer 2: h2 = tanh(W2 @ h1 + b2), thread j owns unit j
                float a0 = b2j, a1 = b2j, a2 = b2j, a3 = b2j;
                const float4* wrow = reinterpret_cast<const float4*>(s.W2p + j * W2S);
                const float4* hp0  = reinterpret_cast<const float4*>(s.h1s + (rg * 4 + 0) * HS);
                const float4* hp1  = reinterpret_cast<const float4*>(s.h1s + (rg * 4 + 1) * HS);
                const float4* hp2  = reinterpret_cast<const float4*>(s.h1s + (rg * 4 + 2) * HS);
                const float4* hp3  = reinterpret_cast<const float4*>(s.h1s + (rg * 4 + 3) * HS);
                #pragma unroll
                for (int kg = 0; kg < 32; kg++) {
                    float4 wv = wrow[kg];
                    float4 v;
                    v = hp0[kg];
                    a0 = fmaf(wv.x, v.x, a0); a0 = fmaf(wv.y, v.y, a0);
                    a0 = fmaf(wv.z, v.z, a0); a0 = fmaf(wv.w, v.w, a0);
                    v = hp1[kg];
                    a1 = fmaf(wv.x, v.x, a1); a1 = fmaf(wv.y, v.y, a1);
                    a1 = fmaf(wv.z, v.z, a1); a1 = fmaf(wv.w, v.w, a1);
                    v = hp2[kg];
                    a2 = fmaf(wv.x, v.x, a2); a2 = fmaf(wv.y, v.y, a2);
                    a2 = fmaf(wv.z, v.z, a2); a2 = fmaf(wv.w, v.w, a2);
                    v = hp3[kg];
                    a3 = fmaf(wv.x, v.x, a3); a3 = fmaf(wv.y, v.y, a3);
                    a3 = fmaf(wv.z, v.z, a3); a3 = fmaf(wv.w, v.w, a3);
                }
                {
                    int rb = rg * 4;
                    if (rb + 0 < nrows) s.h2s[(rb + 0) * HS + j] = tanhf(a0);
                    if (rb + 1 < nrows) s.h2s[(rb + 1) * HS + j] = tanhf(a1);
                    if (rb + 2 < nrows) s.h2s[(rb + 2) * HS + j] = tanhf(a2);
                    if (rb + 3 < nrows) s.h2s[(rb + 3) * HS + j] = tanhf(a3);
                }
                __syncthreads();

                // ---- layer 3 + constraint + gating + RK bookkeeping
                if (tid < nrows * NACT) {
                    int rr = tid / NACT;
                    int i3 = tid - rr * NACT;
                    const float4* w3r = reinterpret_cast<const float4*>(s.W3s + i3 * W3S);
                    const float4* h2r = reinterpret_cast<const float4*>(s.h2s + rr * HS);
                    float ax = 0.f, ay = 0.f, az = 0.f, aw = 0.f;
                    #pragma unroll
                    for (int kg = 0; kg < 32; kg++) {
                        float4 wv = w3r[kg];
                        float4 hv = h2r[kg];
                        ax = fmaf(wv.x, hv.x, ax);
                        ay = fmaf(wv.y, hv.y, ay);
                        az = fmaf(wv.z, hv.z, az);
                        aw = fmaf(wv.w, hv.w, aw);
                    }
                    float acc = ((ax + ay) + (az + aw)) + s.b3s[i3];
                    if (i3 == 0) acc = -cosf(acc);
                    if (t > s.tend[rr]) acc = 0.f;     // per-sample stop
                    if (st == 0)       s.ksum[rr][i3] = acc;
                    else if (st < 3)   s.ksum[rr][i3] += 2.f * acc;
                    if (st < 3) {
                        float cY = (st == 2) ? dtf : 0.5f * dtf;
                        s.Yts[rr][i3] = s.Ycur[rr][i3] + cY * acc;
                    } else {
                        float y = s.Ycur[rr][i3]
                                + (dtf * (1.0f / 6.0f)) * (s.ksum[rr][i3] + acc);
                        s.Ycur[rr][i3] = y;
                        s.Yts[rr][i3]  = y;
                    }
                }
                __syncthreads();
            }
        }
        if (tid < nrows)
            out[(row0 + tid) * Tn + step + 1] = s.Ycur[tid][0];
    }
}

extern "C" void kernel_launch(void* const* d_in, const int* in_sizes, int n_in,
                              void* d_out, int out_size)
{
    (void)in_sizes; (void)n_in; (void)out_size;
    cudaFuncSetAttribute(node_kernel, cudaFuncAttributeMaxDynamicSharedMemorySize,
                         (int)sizeof(Smem));
    node_kernel<<<NCTA, NTH, sizeof(Smem)>>>(
        (const float*)d_in[0],   // ts
        (const float*)d_in[1],   // y0
        (const float*)d_in[2],   // latent_vec
        (const int*)  d_in[3],   // length
        (const float*)d_in[4],   // dense_ts (arange, folded into index math)
        (const float*)d_in[5],   // dense_cs
        (const float*)d_in[6],   // W1
        (const float*)d_in[7],   // b1
        (const float*)d_in[8],   // W2
        (const float*)d_in[9],   // b2
        (const float*)d_in[10],  // W3
        (const float*)d_in[11],  // b3
        (float*)d_out);
}

// round 2
// speedup vs baseline: 1.6004x; 1.6004x over previous
#include <cuda_runtime.h>
#include <math.h>

// ---------------------------------------------------------------------------
// NeuralODE on GB300: B=1024, T=128 saves x 2 RK4 substeps -> 1016 sequential
// vf evals of MLP 43->128->128->41 (only 9 state dims evolve; latent frozen
// -> folded into per-row layer-1 bias).
//
// Round-2 design:
//  * 128 CTAs x 512 threads, 8 rows/CTA (exact: 128*8 = 1024, no tails)
//  * W2 register-resident: thread (unit u, k-half h) holds 64 W2 floats as
//    32 packed f32x2 pairs -> layer-2 uses fma.rn.f32x2 (2 FMA/instr)
//  * smem holds only activations (h1/h2 row-major), W3, per-row constants
//  * fast tanh: 1 - 2/(exp(2x)+1) via ex2.approx+rcp.approx (~1e-7 rel err)
//  * layer-3 parallel: 288 threads (9 units x 8 rows x 4 k-quarters) + shfl
// ---------------------------------------------------------------------------

#define Bsz   1024
#define Tn    128
#define Dn    256
#define NACT  9
#define LATD  32
#define INW   43
#define RR    8
#define NCTA  128
#define NTH   512
#define HP    132   // padded row stride for h1/h2/W3 (floats)

typedef unsigned long long u64;

__device__ __forceinline__ u64 fma2(u64 a, u64 b, u64 c) {
    u64 d;
    asm("fma.rn.f32x2 %0, %1, %2, %3;" : "=l"(d) : "l"(a), "l"(b), "l"(c));
    return d;
}
__device__ __forceinline__ u64 pk2(float lo, float hi) {
    u64 d;
    asm("mov.b64 %0, {%1, %2};" : "=l"(d) : "f"(lo), "f"(hi));
    return d;
}
__device__ __forceinline__ float2 unpk(u64 v) {
    float2 f;
    asm("mov.b64 {%0, %1}, %2;" : "=f"(f.x), "=f"(f.y) : "l"(v));
    return f;
}
// tanh(x) = 1 - 2/(e^{2x}+1); handles +-inf overflow correctly.
__device__ __forceinline__ float tanh_fast(float x) {
    float e = __expf(2.0f * x);
    return 1.0f - __fdividef(2.0f, e + 1.0f);
}

struct __align__(16) Smem {
    float h1row[RR][HP];        // 16B-aligned rows (528 B stride)
    float h2row[RR][HP];
    float W3s[NACT * HP];
    float base1p[128][4][2];    // per-unit, per row-pair folded bias (float2)
    float csp[Dn][4][2];        // concentration, pair-interleaved (float2)
    float Ytsp[4][NACT][2];     // RK stage-input state, pair layout (float2)
    float Ycur[RR][12];
    float ksum[RR][12];
    float b3s[16];
    float tend[RR];
    float tsm[Tn];
};

__global__ __launch_bounds__(NTH, 1)
void node_kernel(const float* __restrict__ ts, const float* __restrict__ y0,
                 const float* __restrict__ latent, const int* __restrict__ length,
                 const float* __restrict__ dense_ts, const float* __restrict__ dense_cs,
                 const float* __restrict__ W1, const float* __restrict__ b1,
                 const float* __restrict__ W2, const float* __restrict__ b2,
                 const float* __restrict__ W3, const float* __restrict__ b3,
                 float* __restrict__ out)
{
    __shared__ Smem s;
    const int tid  = threadIdx.x;
    const int row0 = blockIdx.x * RR;

    // layer-1 mapping: thread = (unit u1, row-pair p)
    const int u1 = tid & 127;
    const int p  = tid >> 7;            // 0..3, rows 2p, 2p+1

    // layer-2 mapping: warp w, lane l; 16 units per warp, h = k-half bit
    const int w  = tid >> 5;
    const int l  = tid & 31;
    const int h  = l >> 4;              // k in [h*64, h*64+64)
    const int u2 = (w & 7) * 16 + (l & 15);
    const int g  = w >> 3;              // rows 4g..4g+3
    const int r0 = 4 * g;

    // ---- one-time setup ---------------------------------------------------
    // W2 register slice: 64 floats = 32 packed f32x2 pairs
    u64 W2r[32];
    {
        const u64* w2g = reinterpret_cast<const u64*>(W2 + u2 * 128 + h * 64);
        #pragma unroll
        for (int m = 0; m < 32; m++) W2r[m] = w2g[m];
    }
    const float b2u = b2[u2];

    // W1 coefficients for layer-1, pre-duplicated as f32x2
    u64 w1d[NACT], w1td, w1cd;
    {
        const float* W1r = W1 + u1 * INW;
        #pragma unroll
        for (int i = 0; i < NACT; i++) w1d[i] = pk2(W1r[i], W1r[i]);
        w1td = pk2(W1r[41], W1r[41]);
        w1cd = pk2(W1r[42], W1r[42]);
        // folded bias: b1 + W1[:,9:41] @ latent, per row of this pair
        #pragma unroll
        for (int e = 0; e < 2; e++) {
            const float* lv = latent + (row0 + 2 * p + e) * LATD;
            float acc = b1[u1];
            #pragma unroll
            for (int li = 0; li < LATD; li++) acc = fmaf(W1r[9 + li], lv[li], acc);
            s.base1p[u1][p][e] = acc;
        }
    }
    // W3 (first 9 rows), b3
    for (int idx = tid; idx < NACT * 128; idx += NTH)
        s.W3s[(idx >> 7) * HP + (idx & 127)] = W3[idx];
    if (tid < NACT) s.b3s[tid] = b3[tid];
    if (tid < Tn)   s.tsm[tid] = ts[tid];
    if (tid < RR) {
        int b  = row0 + tid;
        int li = max(length[b] - 1, 0);
        s.tend[tid] = ts[li];
        float y = y0[b];
        s.Ycur[tid][0] = y;
        s.Ytsp[tid >> 1][0][tid & 1] = y;
        #pragma unroll
        for (int d = 1; d < NACT; d++) {
            s.Ycur[tid][d] = 0.f;
            s.Ytsp[tid >> 1][d][tid & 1] = 0.f;
        }
        out[b * Tn] = y;                 // t = 0 sample
    }
    // concentration rows, pair-interleaved
    for (int idx = tid; idx < RR * Dn; idx += NTH) {
        int r = idx >> 8, d = idx & 255;
        s.csp[d][r >> 1][r & 1] = dense_cs[(row0 + r) * Dn + d];
    }
    __syncthreads();

    // ---- time integration -------------------------------------------------
    for (int step = 0; step < Tn - 1; step++) {
        const float ta  = s.tsm[step];
        const float dtf = (s.tsm[step + 1] - ta) * 0.5f;    // RK4 substep dt
        for (int sub = 0; sub < 2; sub++) {
            const float t0 = ta + sub * dtf;
            for (int st = 0; st < 4; st++) {
                const float t = t0 + ((st == 0) ? 0.f : (st == 3) ? dtf : 0.5f * dtf);

                // ---- layer 1 (packed over row-pair p) ----
                {
                    int ii = (int)ceilf(t);
                    ii = max(1, min(Dn - 1, ii));
                    float wc = t - (float)(ii - 1);
                    wc = fminf(fmaxf(wc, 0.f), 1.f);
                    u64 cl = *reinterpret_cast<const u64*>(&s.csp[ii - 1][p][0]);
                    u64 cr = *reinterpret_cast<const u64*>(&s.csp[ii][p][0]);
                    u64 wd  = pk2(wc, wc);
                    u64 nwd = pk2(-wc, -wc);
                    u64 c2  = fma2(wd, cr, fma2(nwd, cl, cl));
                    u64 acc = *reinterpret_cast<const u64*>(&s.base1p[u1][p][0]);
                    acc = fma2(w1td, pk2(t, t), acc);
                    acc = fma2(w1cd, c2, acc);
                    #pragma unroll
                    for (int i = 0; i < NACT; i++)
                        acc = fma2(w1d[i], *reinterpret_cast<const u64*>(&s.Ytsp[p][i][0]), acc);
                    float2 hv = unpk(acc);
                    s.h1row[2 * p][u1]     = tanh_fast(hv.x);
                    s.h1row[2 * p + 1][u1] = tanh_fast(hv.y);
                }
                __syncthreads();

                // ---- layer 2: register W2, packed k-pairs, 4 rows ----
                {
                    u64 a0 = 0ull, a1 = 0ull, a2 = 0ull, a3 = 0ull;
                    const float* h1b = &s.h1row[r0][0] + h * 64;
                    #pragma unroll
                    for (int m = 0; m < 16; m++) {
                        ulonglong2 v0 = *reinterpret_cast<const ulonglong2*>(h1b + 0 * HP + m * 4);
                        a0 = fma2(W2r[2 * m], v0.x, a0);
                        a0 = fma2(W2r[2 * m + 1], v0.y, a0);
                        ulonglong2 v1 = *reinterpret_cast<const ulonglong2*>(h1b + 1 * HP + m * 4);
                        a1 = fma2(W2r[2 * m], v1.x, a1);
                        a1 = fma2(W2r[2 * m + 1], v1.y, a1);
                        ulonglong2 v2 = *reinterpret_cast<const ulonglong2*>(h1b + 2 * HP + m * 4);
                        a2 = fma2(W2r[2 * m], v2.x, a2);
                        a2 = fma2(W2r[2 * m + 1], v2.y, a2);
                        ulonglong2 v3 = *reinterpret_cast<const ulonglong2*>(h1b + 3 * HP + m * 4);
                        a3 = fma2(W2r[2 * m], v3.x, a3);
                        a3 = fma2(W2r[2 * m + 1], v3.y, a3);
                    }
                    float2 f0 = unpk(a0), f1 = unpk(a1), f2 = unpk(a2), f3 = unpk(a3);
                    float s0 = f0.x + f0.y, s1 = f1.x + f1.y;
                    float s2 = f2.x + f2.y, s3 = f3.x + f3.y;
                    s0 += __shfl_xor_sync(0xffffffffu, s0, 16);
                    s1 += __shfl_xor_sync(0xffffffffu, s1, 16);
                    s2 += __shfl_xor_sync(0xffffffffu, s2, 16);
                    s3 += __shfl_xor_sync(0xffffffffu, s3, 16);
                    float pa = h ? s2 : s0;
                    float pb = h ? s3 : s1;
                    s.h2row[r0 + 2 * h][u2]     = tanh_fast(pa + b2u);
                    s.h2row[r0 + 2 * h + 1][u2] = tanh_fast(pb + b2u);
                }
                __syncthreads();

                // ---- layer 3 + constraint + gating + RK bookkeeping ----
                if (tid < 288) {
                    const int q  = tid & 3;         // k-quarter
                    const int pr = tid >> 2;        // 0..71
                    const int i3 = pr >> 3;         // output unit 0..8
                    const int r  = pr & 7;          // row
                    const float4* wv = reinterpret_cast<const float4*>(&s.W3s[i3 * HP + q * 32]);
                    const float4* hv = reinterpret_cast<const float4*>(&s.h2row[r][q * 32]);
                    float ax = 0.f, ay = 0.f, az = 0.f, aw = 0.f;
                    #pragma unroll
                    for (int kk = 0; kk < 8; kk++) {
                        float4 a = wv[kk], b = hv[kk];
                        ax = fmaf(a.x, b.x, ax);
                        ay = fmaf(a.y, b.y, ay);
                        az = fmaf(a.z, b.z, az);
                        aw = fmaf(a.w, b.w, aw);
                    }
                    float acc = (ax + ay) + (az + aw);
                    acc += __shfl_xor_sync(0xffffffffu, acc, 1);
                    acc += __shfl_xor_sync(0xffffffffu, acc, 2);
                    if (q == 0) {
                        acc += s.b3s[i3];
                        if (i3 == 0) acc = -cosf(acc);
                        if (t > s.tend[r]) acc = 0.f;     // per-sample stop
                        float ks;
                        if (st == 0) { ks = acc; s.ksum[r][i3] = ks; }
                        else {
                            ks = s.ksum[r][i3];
                            if (st < 3) { ks += 2.f * acc; s.ksum[r][i3] = ks; }
                        }
                        if (st < 3) {
                            float cY = (st == 2) ? dtf : 0.5f * dtf;
                            s.Ytsp[r >> 1][i3][r & 1] = s.Ycur[r][i3] + cY * acc;
                        } else {
                            float y = s.Ycur[r][i3]
                                    + (dtf * (1.0f / 6.0f)) * (ks + acc);
                            s.Ycur[r][i3] = y;
                            s.Ytsp[r >> 1][i3][r & 1] = y;
                        }
                    }
                }
                __syncthreads();
            }
        }
        if (tid < RR)
            out[(row0 + tid) * Tn + step + 1] = s.Ycur[tid][0];
    }
}

extern "C" void kernel_launch(void* const* d_in, const int* in_sizes, int n_in,
                              void* d_out, int out_size)
{
    (void)in_sizes; (void)n_in; (void)out_size;
    node_kernel<<<NCTA, NTH>>>(
        (const float*)d_in[0],   // ts
        (const float*)d_in[1],   // y0
        (const float*)d_in[2],   // latent_vec
        (const int*)  d_in[3],   // length
        (const float*)d_in[4],   // dense_ts (arange -> index math)
        (const float*)d_in[5],   // dense_cs
        (const float*)d_in[6],   // W1
        (const float*)d_in[7],   // b1
        (const float*)d_in[8],   // W2
        (const float*)d_in[9],   // b2
        (const float*)d_in[10],  // W3
        (const float*)d_in[11],  // b3
        (float*)d_out);
}

// round 4
// speedup vs baseline: 2.9082x; 1.8172x over previous
#include <cuda_runtime.h>
#include <math.h>

// ---------------------------------------------------------------------------
// NeuralODE on GB300 (round 4 = round 3 + shfl-mask deadlock fix):
//  * 256 CTAs x 256 threads, 4 rows/CTA, 2 CTAs/SM (regs exactly fill RF)
//  * rows counting-sorted by length; CTA skips all vf math once
//    ts[step] > max(t_end of its rows)  (saves ~50% of the evals)
//  * antithetic rank pairing: bids b and b+148 share an SM -> pair short+long
//  * W2 register-resident as packed f32x2; fma.rn.f32x2 everywhere hot
//  * tanh via MUFU tanh.approx.f32
//  * layer-3 uses 144 threads = 4.5 warps -> per-warp participation mask
//    (round 3 hung: 0xffffffff mask with 16 inactive lanes in warp 4)
// ---------------------------------------------------------------------------

#define Bsz   1024
#define Tn    128
#define Dn    256
#define NACT  9
#define LATD  32
#define INW   43
#define RR    4      // rows per CTA
#define NCTA  256
#define NTH   256
#define HP    132    // padded row stride (floats)

typedef unsigned long long u64;

__device__ int g_perm[Bsz];

__device__ __forceinline__ u64 fma2(u64 a, u64 b, u64 c) {
    u64 d;
    asm("fma.rn.f32x2 %0, %1, %2, %3;" : "=l"(d) : "l"(a), "l"(b), "l"(c));
    return d;
}
__device__ __forceinline__ u64 pk2(float lo, float hi) {
    u64 d;
    asm("mov.b64 %0, {%1, %2};" : "=l"(d) : "f"(lo), "f"(hi));
    return d;
}
__device__ __forceinline__ float2 unpk(u64 v) {
    float2 f;
    asm("mov.b64 {%0, %1}, %2;" : "=f"(f.x), "=f"(f.y) : "l"(v));
    return f;
}
__device__ __forceinline__ float tanh_fast(float x) {
    float r;
    asm("tanh.approx.f32 %0, %1;" : "=f"(r) : "f"(x));
    return r;
}

// ---- counting sort of rows by length (stable, deterministic) --------------
__global__ void sort_kernel(const int* __restrict__ length)
{
    __shared__ int len_s[Bsz];
    __shared__ int hist[Tn];
    __shared__ int pref[Tn];
    const int tid = threadIdx.x;          // 128 threads
    for (int i = tid; i < Bsz; i += 128) {
        int v = length[i];
        len_s[i] = min(max(v, 0), Tn - 1);
    }
    if (tid < Tn) hist[tid] = 0;
    __syncthreads();
    for (int i = tid; i < Bsz; i += 128) atomicAdd(&hist[len_s[i]], 1);
    __syncthreads();
    if (tid == 0) {
        int acc = 0;
        for (int v = 0; v < Tn; v++) { pref[v] = acc; acc += hist[v]; }
    }
    __syncthreads();
    int pos = pref[tid];                  // thread tid handles bin value tid
    for (int b = 0; b < Bsz; b++)
        if (len_s[b] == tid) g_perm[pos++] = b;
}

struct __align__(16) Smem {
    float h1row[RR][HP];
    float h2row[RR][HP];
    float W3s[NACT * HP];
    float base1p[128][2][2];   // (unit, row-pair, elem)
    float csp[Dn][2][2];       // (time idx, row-pair, elem)
    float Ytsp[2][NACT][2];    // RK stage-input state (row-pair packed)
    float Ycur[RR][12];
    float ksum[RR][12];
    float b3s[16];
    float tend[RR];
    float tendmax;
    int   brow[RR];
    float tsm[Tn];
};

__global__ __launch_bounds__(NTH, 2)
void node_kernel(const float* __restrict__ ts, const float* __restrict__ y0,
                 const float* __restrict__ latent, const int* __restrict__ length,
                 const float* __restrict__ dense_ts, const float* __restrict__ dense_cs,
                 const float* __restrict__ W1, const float* __restrict__ b1,
                 const float* __restrict__ W2, const float* __restrict__ b2,
                 const float* __restrict__ W3, const float* __restrict__ b3,
                 float* __restrict__ out)
{
    __shared__ Smem s;
    const int tid = threadIdx.x;
    const int bid = blockIdx.x;
    // antithetic pairing: bid and bid+148 land on the same SM (classic LUT),
    // so give them rank-groups grp and 255-grp -> short+long balance.
    const int grp = (bid < 148) ? bid : (403 - bid);

    // layer-1 mapping
    const int u1 = tid & 127;
    const int p  = tid >> 7;               // row-pair 0..1

    // layer-2 mapping
    const int w  = tid >> 5;               // warp 0..7
    const int l  = tid & 31;
    const int h  = l >> 4;                 // k-half
    const int u2 = w * 16 + (l & 15);

    // ---- one-time setup ---------------------------------------------------
    u64 W2r[32];
    {
        const u64* w2g = reinterpret_cast<const u64*>(W2 + u2 * 128 + h * 64);
        #pragma unroll
        for (int m = 0; m < 32; m++) W2r[m] = w2g[m];
    }
    const float b2u = b2[u2];

    if (tid < RR) s.brow[tid] = g_perm[grp * RR + tid];
    if (tid < Tn) s.tsm[tid] = ts[tid];
    for (int idx = tid; idx < NACT * 128; idx += NTH)
        s.W3s[(idx >> 7) * HP + (idx & 127)] = W3[idx];
    if (tid < NACT) s.b3s[tid] = b3[tid];
    __syncthreads();

    if (tid < RR) {
        int b  = s.brow[tid];
        int li = max(length[b] - 1, 0);
        s.tend[tid] = ts[li];
        float y = y0[b];
        s.Ycur[tid][0] = y;
        s.Ytsp[tid >> 1][0][tid & 1] = y;
        #pragma unroll
        for (int d = 1; d < NACT; d++) {
            s.Ycur[tid][d] = 0.f;
            s.Ytsp[tid >> 1][d][tid & 1] = 0.f;
        }
        out[b * Tn] = y;                    // t = 0 sample
    }
    for (int idx = tid; idx < RR * Dn; idx += NTH) {
        int r = idx >> 8, d = idx & 255;
        s.csp[d][r >> 1][r & 1] = dense_cs[s.brow[r] * Dn + d];
    }
    // W1 coefficients, pre-duplicated; folded latent bias per row of the pair
    u64 w1d[NACT], w1td, w1cd;
    {
        const float* W1r = W1 + u1 * INW;
        #pragma unroll
        for (int i = 0; i < NACT; i++) w1d[i] = pk2(W1r[i], W1r[i]);
        w1td = pk2(W1r[41], W1r[41]);
        w1cd = pk2(W1r[42], W1r[42]);
        #pragma unroll
        for (int e = 0; e < 2; e++) {
            const float* lv = latent + s.brow[2 * p + e] * LATD;
            float acc = b1[u1];
            #pragma unroll
            for (int li = 0; li < LATD; li++) acc = fmaf(W1r[9 + li], lv[li], acc);
            s.base1p[u1][p][e] = acc;
        }
    }
    __syncthreads();
    if (tid == 0) {
        float m = s.tend[0];
        #pragma unroll
        for (int r = 1; r < RR; r++) m = fmaxf(m, s.tend[r]);
        s.tendmax = m;
    }
    __syncthreads();

    // ---- time integration -------------------------------------------------
    for (int step = 0; step < Tn - 1; step++) {
        const float ta  = s.tsm[step];
        const float dtf = (s.tsm[step + 1] - ta) * 0.5f;
        if (ta <= s.tendmax) {
            for (int sub = 0; sub < 2; sub++) {
                const float t0 = ta + sub * dtf;
                for (int st = 0; st < 4; st++) {
                    const float t = t0 + ((st == 0) ? 0.f : (st == 3) ? dtf : 0.5f * dtf);

                    // ---- layer 1 (row-pair packed) ----
                    {
                        int ii = (int)ceilf(t);
                        ii = max(1, min(Dn - 1, ii));
                        float wc = t - (float)(ii - 1);
                        wc = fminf(fmaxf(wc, 0.f), 1.f);
                        u64 cl = *reinterpret_cast<const u64*>(&s.csp[ii - 1][p][0]);
                        u64 cr = *reinterpret_cast<const u64*>(&s.csp[ii][p][0]);
                        u64 wd  = pk2(wc, wc);
                        u64 nwd = pk2(-wc, -wc);
                        u64 c2  = fma2(wd, cr, fma2(nwd, cl, cl));
                        u64 acc = *reinterpret_cast<const u64*>(&s.base1p[u1][p][0]);
                        acc = fma2(w1td, pk2(t, t), acc);
                        acc = fma2(w1cd, c2, acc);
                        #pragma unroll
                        for (int i = 0; i < NACT; i++)
                            acc = fma2(w1d[i],
                                       *reinterpret_cast<const u64*>(&s.Ytsp[p][i][0]), acc);
                        float2 hv = unpk(acc);
                        s.h1row[2 * p][u1]     = tanh_fast(hv.x);
                        s.h1row[2 * p + 1][u1] = tanh_fast(hv.y);
                    }
                    __syncthreads();

                    // ---- layer 2: register W2, packed k-pairs, 4 rows ----
                    {
                        u64 a0 = 0ull, a1 = 0ull, a2 = 0ull, a3 = 0ull;
                        const float* h1b = &s.h1row[0][0] + h * 64;
                        #pragma unroll
                        for (int m = 0; m < 16; m++) {
                            ulonglong2 v0 = *reinterpret_cast<const ulonglong2*>(h1b + 0 * HP + m * 4);
                            a0 = fma2(W2r[2 * m],     v0.x, a0);
                            a0 = fma2(W2r[2 * m + 1], v0.y, a0);
                            ulonglong2 v1 = *reinterpret_cast<const ulonglong2*>(h1b + 1 * HP + m * 4);
                            a1 = fma2(W2r[2 * m],     v1.x, a1);
                            a1 = fma2(W2r[2 * m + 1], v1.y, a1);
                            ulonglong2 v2 = *reinterpret_cast<const ulonglong2*>(h1b + 2 * HP + m * 4);
                            a2 = fma2(W2r[2 * m],     v2.x, a2);
                            a2 = fma2(W2r[2 * m + 1], v2.y, a2);
                            ulonglong2 v3 = *reinterpret_cast<const ulonglong2*>(h1b + 3 * HP + m * 4);
                            a3 = fma2(W2r[2 * m],     v3.x, a3);
                            a3 = fma2(W2r[2 * m + 1], v3.y, a3);
                        }
                        float2 f0 = unpk(a0), f1 = unpk(a1), f2 = unpk(a2), f3 = unpk(a3);
                        float s0 = f0.x + f0.y, s1 = f1.x + f1.y;
                        float s2 = f2.x + f2.y, s3 = f3.x + f3.y;
                        s0 += __shfl_xor_sync(0xffffffffu, s0, 16);
                        s1 += __shfl_xor_sync(0xffffffffu, s1, 16);
                        s2 += __shfl_xor_sync(0xffffffffu, s2, 16);
                        s3 += __shfl_xor_sync(0xffffffffu, s3, 16);
                        float pa = h ? s2 : s0;
                        float pb = h ? s3 : s1;
                        s.h2row[2 * h][u2]     = tanh_fast(pa + b2u);
                        s.h2row[2 * h + 1][u2] = tanh_fast(pb + b2u);
                    }
                    __syncthreads();

                    // ---- layer 3 + constraint + gating + RK bookkeeping ----
                    // 144 threads = warps 0..3 fully + lanes 0..15 of warp 4.
                    // Mask MUST name exactly the participating lanes.
                    if (tid < 144) {
                        const unsigned mask = (tid < 128) ? 0xffffffffu : 0x0000ffffu;
                        const int q  = tid & 3;      // k-quarter
                        const int pr = tid >> 2;     // 0..35
                        const int r  = pr & 3;       // row
                        const int i3 = pr >> 2;      // output unit 0..8
                        const float4* wv = reinterpret_cast<const float4*>(&s.W3s[i3 * HP + q * 32]);
                        const float4* hv = reinterpret_cast<const float4*>(&s.h2row[r][q * 32]);
                        float ax = 0.f, ay = 0.f, az = 0.f, aw = 0.f;
                        #pragma unroll
                        for (int kk = 0; kk < 8; kk++) {
                            float4 a = wv[kk], b = hv[kk];
                            ax = fmaf(a.x, b.x, ax);
                            ay = fmaf(a.y, b.y, ay);
                            az = fmaf(a.z, b.z, az);
                            aw = fmaf(a.w, b.w, aw);
                        }
                        float acc = (ax + ay) + (az + aw);
                        acc += __shfl_xor_sync(mask, acc, 1);
                        acc += __shfl_xor_sync(mask, acc, 2);
                        if (q == 0) {
                            acc += s.b3s[i3];
                            if (i3 == 0) acc = -__cosf(acc);
                            if (t > s.tend[r]) acc = 0.f;   // per-sample stop
                            float ks;
                            if (st == 0) { ks = acc; s.ksum[r][i3] = ks; }
                            else {
                                ks = s.ksum[r][i3];
                                if (st < 3) { ks += 2.f * acc; s.ksum[r][i3] = ks; }
                            }
                            if (st < 3) {
                                float cY = (st == 2) ? dtf : 0.5f * dtf;
                                s.Ytsp[r >> 1][i3][r & 1] = s.Ycur[r][i3] + cY * acc;
                            } else {
                                float y = s.Ycur[r][i3]
                                        + (dtf * (1.0f / 6.0f)) * (ks + acc);
                                s.Ycur[r][i3] = y;
                                s.Ytsp[r >> 1][i3][r & 1] = y;
                            }
                        }
                    }
                    __syncthreads();
                }
            }
        }
        if (tid < RR)
            out[s.brow[tid] * Tn + step + 1] = s.Ycur[tid][0];
    }
}

extern "C" void kernel_launch(void* const* d_in, const int* in_sizes, int n_in,
                              void* d_out, int out_size)
{
    (void)in_sizes; (void)n_in; (void)out_size;
    sort_kernel<<<1, 128>>>((const int*)d_in[3]);
    node_kernel<<<NCTA, NTH>>>(
        (const float*)d_in[0],   // ts
        (const float*)d_in[1],   // y0
        (const float*)d_in[2],   // latent_vec
        (const int*)  d_in[3],   // length
        (const float*)d_in[4],   // dense_ts (arange -> index math)
        (const float*)d_in[5],   // dense_cs
        (const float*)d_in[6],   // W1
        (const float*)d_in[7],   // b1
        (const float*)d_in[8],   // W2
        (const float*)d_in[9],   // b2
        (const float*)d_in[10],  // W3
        (const float*)d_in[11],  // b3
        (float*)d_out);
}